// round 1
// baseline (speedup 1.0000x reference)
#include <cuda_runtime.h>

#define PAIRS_PER_BLOCK 8
#define NTHREADS (PAIRS_PER_BLOCK * 8)

__device__ __forceinline__ float lrelu(float x) { return x > 0.0f ? x : 0.01f * x; }

__global__ void __launch_bounds__(NTHREADS)
gcn_kernel(const float* __restrict__ x,   const float* __restrict__ adj,
           const float* __restrict__ edge,
           const float* __restrict__ wb,  const float* __restrict__ bb,
           const float* __restrict__ w1,  const float* __restrict__ b1,
           const float* __restrict__ w2,  const float* __restrict__ b2,
           const float* __restrict__ wg,  const float* __restrict__ bg,
           const float* __restrict__ wf,  const float* __restrict__ bf,
           float* __restrict__ out)
{
    // per-pair exchange buffers (float2 packs batch pair), padded vs. bank conflicts
    __shared__ float2 s_Fk[PAIRS_PER_BLOCK][8][9];
    __shared__ float2 s_W [PAIRS_PER_BLOCK][8][9];
    __shared__ float2 s_p [PAIRS_PER_BLOCK][8][17];
    __shared__ float2 s_q [PAIRS_PER_BLOCK][8][9];
    __shared__ float2 s_h2[PAIRS_PER_BLOCK][8][9];
    __shared__ float2 s_ty[PAIRS_PER_BLOCK][8];
    __shared__ float2 s_xp[PAIRS_PER_BLOCK][8];
    // weights (broadcast reads -> no padding needed)
    __shared__ float s_wb[8][32];
    __shared__ float s_w1[32][16];
    __shared__ float s_w2[16][8];
    __shared__ float s_wg[8][8];
    __shared__ float s_bb[8], s_b1[16], s_b2[8], s_bg[8], s_wf[16], s_bf[2];

    const int tid = threadIdx.x;

    // stage weights
    for (int i = tid; i < 256; i += NTHREADS) ((float*)s_wb)[i] = wb[i];
    for (int i = tid; i < 512; i += NTHREADS) ((float*)s_w1)[i] = w1[i];
    for (int i = tid; i < 128; i += NTHREADS) ((float*)s_w2)[i] = w2[i];
    if (tid < 64) ((float*)s_wg)[tid] = wg[tid];
    if (tid < 16) { s_b1[tid] = b1[tid]; s_wf[tid] = wf[tid]; }
    if (tid < 8)  { s_bb[tid] = bb[tid]; s_b2[tid] = b2[tid]; s_bg[tid] = bg[tid]; }
    if (tid < 2)  { s_bf[tid] = bf[tid]; }
    __syncthreads();

    const int g = tid >> 3;   // pair within block
    const int v = tid & 7;    // node index (also reused as pool output channel o)
    const size_t pair = (size_t)blockIdx.x * PAIRS_PER_BLOCK + g;
    const size_t b0 = pair * 2;

    const float* x0 = x + b0 * 264 + (size_t)v * 33;
    const float* x1 = x0 + 264;
    const float2 ty = make_float2(x0[0], x1[0]);

    // ---- Fk column v  (Fk[o,v] = dot(feat[v], wb[o]) + bb[o])
    // ---- p row v      (p = feat @ w1, so h1 = lrelu(W @ p + b1))
    float2 Fkc[8];
    float2 p[16];
    #pragma unroll
    for (int o = 0; o < 8; o++) Fkc[o] = make_float2(s_bb[o], s_bb[o]);
    #pragma unroll
    for (int j = 0; j < 16; j++) p[j] = make_float2(0.f, 0.f);
    #pragma unroll
    for (int c = 0; c < 32; c++) {
        float2 fc = make_float2(x0[1 + c], x1[1 + c]);
        #pragma unroll
        for (int o = 0; o < 8; o++) {
            float w = s_wb[o][c];
            Fkc[o].x += fc.x * w; Fkc[o].y += fc.y * w;
        }
        #pragma unroll
        for (int j = 0; j < 16; j++) {
            float w = s_w1[c][j];
            p[j].x += fc.x * w; p[j].y += fc.y * w;
        }
    }
    #pragma unroll
    for (int o = 0; o < 8; o++) s_Fk[g][o][v] = Fkc[o];
    #pragma unroll
    for (int j = 0; j < 16; j++) s_p[g][v][j] = p[j];
    __syncwarp();

    // ---- M column v: M[i] = sum_k Fk[i,k] * Fk[k,v];  softmax over i (local)
    float2 Mv[8];
    #pragma unroll
    for (int i = 0; i < 8; i++) {
        float a0 = 0.f, a1 = 0.f;
        #pragma unroll
        for (int k = 0; k < 8; k++) {
            float2 fik = s_Fk[g][i][k];
            a0 += fik.x * Fkc[k].x; a1 += fik.y * Fkc[k].y;
        }
        Mv[i] = make_float2(a0, a1);
    }
    float mx0 = -1e30f, mx1 = -1e30f;
    #pragma unroll
    for (int i = 0; i < 8; i++) { mx0 = fmaxf(mx0, Mv[i].x); mx1 = fmaxf(mx1, Mv[i].y); }
    float se0 = 0.f, se1 = 0.f;
    #pragma unroll
    for (int i = 0; i < 8; i++) {
        Mv[i].x = __expf(Mv[i].x - mx0); Mv[i].y = __expf(Mv[i].y - mx1);
        se0 += Mv[i].x; se1 += Mv[i].y;
    }
    const float inv0 = 1.f / se0, inv1 = 1.f / se1;

    // ---- W column v: W[i,v] = adj[i,v] * (S[i,v] + edge[i,v])
    const float* a0p = adj  + b0 * 64 + v;
    const float* e0p = edge + b0 * 64 + v;
    #pragma unroll
    for (int i = 0; i < 8; i++) {
        float wv0 = a0p[i * 8]      * (Mv[i].x * inv0 + e0p[i * 8]);
        float wv1 = a0p[64 + i * 8] * (Mv[i].y * inv1 + e0p[64 + i * 8]);
        s_W[g][i][v] = make_float2(wv0, wv1);
    }
    __syncwarp();

    // ---- h1 row v = lrelu( sum_w W[v,w] * p[w,:] + b1 )
    float2 h1[16];
    #pragma unroll
    for (int j = 0; j < 16; j++) h1[j] = make_float2(0.f, 0.f);
    #pragma unroll
    for (int w = 0; w < 8; w++) {
        float2 Wv = s_W[g][v][w];
        #pragma unroll
        for (int j = 0; j < 16; j++) {
            float2 pw = s_p[g][w][j];
            h1[j].x += Wv.x * pw.x; h1[j].y += Wv.y * pw.y;
        }
    }
    #pragma unroll
    for (int j = 0; j < 16; j++) {
        float b = s_b1[j];
        h1[j].x = lrelu(h1[j].x + b); h1[j].y = lrelu(h1[j].y + b);
    }

    // ---- q row v = h1[v,:] @ w2   (so h2 = lrelu(W @ q + b2))
    float2 q[8];
    #pragma unroll
    for (int k = 0; k < 8; k++) q[k] = make_float2(0.f, 0.f);
    #pragma unroll
    for (int j = 0; j < 16; j++) {
        float2 hj = h1[j];
        #pragma unroll
        for (int k = 0; k < 8; k++) {
            float w = s_w2[j][k];
            q[k].x += hj.x * w; q[k].y += hj.y * w;
        }
    }
    #pragma unroll
    for (int k = 0; k < 8; k++) s_q[g][v][k] = q[k];
    __syncwarp();

    // ---- h2 row v = lrelu( sum_w W[v,w] * q[w,:] + b2 )
    float2 h2[8];
    #pragma unroll
    for (int k = 0; k < 8; k++) h2[k] = make_float2(0.f, 0.f);
    #pragma unroll
    for (int w = 0; w < 8; w++) {
        float2 Wv = s_W[g][v][w];
        #pragma unroll
        for (int k = 0; k < 8; k++) {
            float2 qw = s_q[g][w][k];
            h2[k].x += Wv.x * qw.x; h2[k].y += Wv.y * qw.y;
        }
    }
    #pragma unroll
    for (int k = 0; k < 8; k++) {
        float b = s_b2[k];
        h2[k].x = lrelu(h2[k].x + b); h2[k].y = lrelu(h2[k].y + b);
        s_h2[g][v][k] = h2[k];
    }
    s_ty[g][v] = ty;
    __syncwarp();

    // ---- attention pooling: this thread computes pooled channel o = v.
    // gate logits L[u] = mask(u)*dot(h2[u,:], wg[o,:]) + bg[o]; softmax over u.
    // d[u] (the dot) is mask/t independent -> compute once.
    float2 d[8], ho[8], tyu[8];
    #pragma unroll
    for (int u = 0; u < 8; u++) {
        tyu[u] = s_ty[g][u];
        float dx = 0.f, dy = 0.f;
        #pragma unroll
        for (int c = 0; c < 8; c++) {
            float w = s_wg[v][c];
            float2 hh = s_h2[g][u][c];
            dx += hh.x * w; dy += hh.y * w;
        }
        d[u]  = make_float2(dx, dy);
        ho[u] = s_h2[g][u][v];
    }
    const float bgv = s_bg[v];
    float xp0 = 0.f, xp1 = 0.f;
    #pragma unroll
    for (int t = 0; t < 2; t++) {
        float tf = (float)t;
        float L0[8], L1[8], hm0[8], hm1[8];
        float m0 = -1e30f, m1 = -1e30f;
        #pragma unroll
        for (int u = 0; u < 8; u++) {
            float ma = (tyu[u].x == tf) ? 1.f : 0.f;
            float mb = (tyu[u].y == tf) ? 1.f : 0.f;
            L0[u] = ma * d[u].x + bgv; L1[u] = mb * d[u].y + bgv;
            hm0[u] = ma * ho[u].x;     hm1[u] = mb * ho[u].y;
            m0 = fmaxf(m0, L0[u]);     m1 = fmaxf(m1, L1[u]);
        }
        float s0 = 0.f, s1 = 0.f, n0 = 0.f, n1 = 0.f;
        #pragma unroll
        for (int u = 0; u < 8; u++) {
            float e0 = __expf(L0[u] - m0), e1 = __expf(L1[u] - m1);
            s0 += e0; s1 += e1;
            n0 += e0 * hm0[u]; n1 += e1 * hm1[u];
        }
        xp0 += n0 / s0; xp1 += n1 / s1;
    }
    s_xp[g][v] = make_float2(0.5f * xp0, 0.5f * xp1);
    __syncwarp();

    // ---- final: out[b, n] = sum_o xp[o] * wf[n, o] + bf[n]
    if (v < 2) {
        float o0 = s_bf[v], o1 = s_bf[v];
        #pragma unroll
        for (int o = 0; o < 8; o++) {
            float w = s_wf[v * 8 + o];
            float2 xpv = s_xp[g][o];
            o0 += xpv.x * w; o1 += xpv.y * w;
        }
        out[b0 * 2 + v]     = o0;
        out[b0 * 2 + 2 + v] = o1;
    }
}

extern "C" void kernel_launch(void* const* d_in, const int* in_sizes, int n_in,
                              void* d_out, int out_size)
{
    const float* x    = (const float*)d_in[0];
    const float* adj  = (const float*)d_in[1];
    const float* edge = (const float*)d_in[2];
    // d_in[3] = wa, d_in[4] = ba  -- unused by the reference
    const float* wb = (const float*)d_in[5];
    const float* bb = (const float*)d_in[6];
    const float* w1 = (const float*)d_in[7];
    const float* b1 = (const float*)d_in[8];
    const float* w2 = (const float*)d_in[9];
    const float* b2 = (const float*)d_in[10];
    const float* wg = (const float*)d_in[11];
    const float* bg = (const float*)d_in[12];
    const float* wf = (const float*)d_in[13];
    const float* bf = (const float*)d_in[14];

    const int B = in_sizes[0] / 264;                 // x is (B, 8, 33)
    const int grid = B / (2 * PAIRS_PER_BLOCK);      // 2 batches per pair, 8 pairs/block
    gcn_kernel<<<grid, NTHREADS>>>(x, adj, edge, wb, bb, w1, b1, w2, b2,
                                   wg, bg, wf, bf, (float*)d_out);
}

// round 2
// speedup vs baseline: 1.5469x; 1.5469x over previous
#include <cuda_runtime.h>

#define PAIRS_PER_BLOCK 8
#define NTHREADS (PAIRS_PER_BLOCK * 8)
#define SLOT 584

typedef unsigned long long u64;

__device__ __forceinline__ u64 pk2(float a, float b) {
    u64 r; asm("mov.b64 %0,{%1,%2};" : "=l"(r) : "f"(a), "f"(b)); return r;
}
__device__ __forceinline__ u64 pk1(float a) { return pk2(a, a); }
__device__ __forceinline__ void up2(u64 v, float& a, float& b) {
    asm("mov.b64 {%0,%1},%2;" : "=f"(a), "=f"(b) : "l"(v));
}
__device__ __forceinline__ u64 fma2_(u64 a, u64 b, u64 c) {
    u64 d; asm("fma.rn.f32x2 %0,%1,%2,%3;" : "=l"(d) : "l"(a), "l"(b), "l"(c)); return d;
}
__device__ __forceinline__ u64 add2_(u64 a, u64 b) {
    u64 d; asm("add.rn.f32x2 %0,%1,%2;" : "=l"(d) : "l"(a), "l"(b)); return d;
}
__device__ __forceinline__ u64 mul2_(u64 a, u64 b) {
    u64 d; asm("mul.rn.f32x2 %0,%1,%2;" : "=l"(d) : "l"(a), "l"(b)); return d;
}
__device__ __forceinline__ float lrelu(float x) { return fmaxf(x, 0.01f * x); }

__global__ void __launch_bounds__(NTHREADS, 9)
gcn_kernel(const float* __restrict__ x,   const float* __restrict__ adj,
           const float* __restrict__ edge,
           const float* __restrict__ wb,  const float* __restrict__ bb,
           const float* __restrict__ w1,  const float* __restrict__ b1,
           const float* __restrict__ w2,  const float* __restrict__ b2,
           const float* __restrict__ wg,  const float* __restrict__ bg,
           const float* __restrict__ wf,  const float* __restrict__ bf,
           float* __restrict__ out)
{
    // Union region: per pair slot of SLOT floats.
    // Phase A (x stage): feat[b][c][v] at b*256 + c*8 + v (transposed), type at 512 + b*8 + v
    // Phase B (aliased): FkT rows at 0, S->q rows at 128, p->h2 rows at 256, xp at 528
    __shared__ __align__(16) float s_u[PAIRS_PER_BLOCK * SLOT];
    __shared__ __align__(16) float s_w1[32][16];
    __shared__ __align__(16) float s_wbT[32][8];
    __shared__ __align__(16) float s_w2[16][8];
    __shared__ __align__(16) float s_wg[8][8];
    __shared__ __align__(16) float s_bb[8];
    __shared__ __align__(16) float s_b1[16];
    __shared__ __align__(16) float s_b2[8];
    __shared__ float s_bg[8], s_wf[16], s_bf[2];

    const int tid = threadIdx.x;

    for (int i = tid; i < 512; i += NTHREADS) ((float*)s_w1)[i] = w1[i];
    for (int i = tid; i < 256; i += NTHREADS) {
        int c = i >> 3, o = i & 7;
        s_wbT[c][o] = wb[o * 32 + c];
    }
    for (int i = tid; i < 128; i += NTHREADS) ((float*)s_w2)[i] = w2[i];
    if (tid < 64) ((float*)s_wg)[tid] = wg[tid];
    if (tid < 16) { s_b1[tid] = b1[tid]; s_wf[tid] = wf[tid]; }
    if (tid < 8)  { s_bb[tid] = bb[tid]; s_b2[tid] = b2[tid]; s_bg[tid] = bg[tid]; }
    if (tid < 2)  { s_bf[tid] = bf[tid]; }

    {   // stage x tile: coalesced float4 reads, transposed scatter into smem
        const float4* xsrc = (const float4*)(x + (size_t)blockIdx.x * (PAIRS_PER_BLOCK * 2 * 264));
        #pragma unroll 1
        for (int i = tid; i < PAIRS_PER_BLOCK * 2 * 264 / 4; i += NTHREADS) {
            float4 t = xsrc[i];
            int s = i * 4;
            float e[4] = {t.x, t.y, t.z, t.w};
            #pragma unroll
            for (int k = 0; k < 4; k++) {
                int ss = s + k;
                int bl = ss / 264;
                int rem = ss - bl * 264;
                int node = rem / 33;
                int col = rem - node * 33;
                int pr = bl >> 1, b = bl & 1;
                int dst = pr * SLOT + (col == 0 ? 512 + b * 8 + node
                                               : b * 256 + (col - 1) * 8 + node);
                s_u[dst] = e[k];
            }
        }
    }
    __syncthreads();

    const int g = tid >> 3;
    const int v = tid & 7;
    const size_t pair = (size_t)blockIdx.x * PAIRS_PER_BLOCK + g;
    const size_t b0 = pair * 2;
    float* Xg = s_u + g * SLOT;

    // ================= phase 1: Fk column v (o-paired), p row v (j-paired)
    u64 Fk[2][4], p[2][8];
    #pragma unroll
    for (int i = 0; i < 4; i++) { Fk[0][i] = 0ull; Fk[1][i] = 0ull; }
    #pragma unroll
    for (int i = 0; i < 8; i++) { p[0][i] = 0ull; p[1][i] = 0ull; }

    #pragma unroll 8
    for (int c = 0; c < 32; c++) {
        float fc0 = Xg[c * 8 + v];
        float fc1 = Xg[256 + c * 8 + v];
        u64 q0 = pk1(fc0), q1 = pk1(fc1);
        const ulonglong2* w1r = (const ulonglong2*)s_w1[c];
        const ulonglong2* wbr = (const ulonglong2*)s_wbT[c];
        #pragma unroll
        for (int jj = 0; jj < 4; jj++) {
            ulonglong2 w = w1r[jj];
            p[0][jj * 2]     = fma2_(q0, w.x, p[0][jj * 2]);
            p[0][jj * 2 + 1] = fma2_(q0, w.y, p[0][jj * 2 + 1]);
            p[1][jj * 2]     = fma2_(q1, w.x, p[1][jj * 2]);
            p[1][jj * 2 + 1] = fma2_(q1, w.y, p[1][jj * 2 + 1]);
        }
        #pragma unroll
        for (int oo = 0; oo < 2; oo++) {
            ulonglong2 w = wbr[oo];
            Fk[0][oo * 2]     = fma2_(q0, w.x, Fk[0][oo * 2]);
            Fk[0][oo * 2 + 1] = fma2_(q0, w.y, Fk[0][oo * 2 + 1]);
            Fk[1][oo * 2]     = fma2_(q1, w.x, Fk[1][oo * 2]);
            Fk[1][oo * 2 + 1] = fma2_(q1, w.y, Fk[1][oo * 2 + 1]);
        }
    }
    #pragma unroll
    for (int i = 0; i < 4; i++) {
        u64 bbp = ((const u64*)s_bb)[i];
        Fk[0][i] = add2_(Fk[0][i], bbp);
        Fk[1][i] = add2_(Fk[1][i], bbp);
    }

    __syncwarp();
    {
        u64* d0 = (u64*)Xg + v * 4;
        u64* d1 = (u64*)Xg + 32 + v * 4;
        #pragma unroll
        for (int i = 0; i < 4; i++) { d0[i] = Fk[0][i]; d1[i] = Fk[1][i]; }
        u64* p0 = (u64*)(Xg + 256) + v * 8;
        u64* p1 = (u64*)(Xg + 256) + 64 + v * 8;
        #pragma unroll
        for (int i = 0; i < 8; i++) { p0[i] = p[0][i]; p1[i] = p[1][i]; }
    }
    __syncwarp();

    // ================= M column v, softmax over rows i, write S rows
    {
        float fks[2][8];
        #pragma unroll
        for (int i = 0; i < 4; i++) {
            up2(Fk[0][i], fks[0][2 * i], fks[0][2 * i + 1]);
            up2(Fk[1][i], fks[1][2 * i], fks[1][2 * i + 1]);
        }
        u64 Mv[2][4];
        #pragma unroll
        for (int i = 0; i < 4; i++) { Mv[0][i] = 0ull; Mv[1][i] = 0ull; }
        #pragma unroll
        for (int k = 0; k < 8; k++) {
            ulonglong2 r0a = *(const ulonglong2*)(Xg + k * 8);
            ulonglong2 r0b = *(const ulonglong2*)(Xg + k * 8 + 4);
            ulonglong2 r1a = *(const ulonglong2*)(Xg + 64 + k * 8);
            ulonglong2 r1b = *(const ulonglong2*)(Xg + 64 + k * 8 + 4);
            u64 s0 = pk1(fks[0][k]), s1 = pk1(fks[1][k]);
            Mv[0][0] = fma2_(s0, r0a.x, Mv[0][0]);
            Mv[0][1] = fma2_(s0, r0a.y, Mv[0][1]);
            Mv[0][2] = fma2_(s0, r0b.x, Mv[0][2]);
            Mv[0][3] = fma2_(s0, r0b.y, Mv[0][3]);
            Mv[1][0] = fma2_(s1, r1a.x, Mv[1][0]);
            Mv[1][1] = fma2_(s1, r1a.y, Mv[1][1]);
            Mv[1][2] = fma2_(s1, r1b.x, Mv[1][2]);
            Mv[1][3] = fma2_(s1, r1b.y, Mv[1][3]);
        }
        #pragma unroll
        for (int b = 0; b < 2; b++) {
            float m[8];
            #pragma unroll
            for (int i = 0; i < 4; i++) up2(Mv[b][i], m[2 * i], m[2 * i + 1]);
            float mx = m[0];
            #pragma unroll
            for (int i = 1; i < 8; i++) mx = fmaxf(mx, m[i]);
            float se = 0.f;
            #pragma unroll
            for (int i = 0; i < 8; i++) { m[i] = __expf(m[i] - mx); se += m[i]; }
            float inv = 1.f / se;
            #pragma unroll
            for (int i = 0; i < 8; i++) Xg[128 + b * 64 + i * 8 + v] = m[i] * inv;
        }
    }
    __syncwarp();

    // ================= W row v in registers
    float Wr[2][8];
    #pragma unroll
    for (int b = 0; b < 2; b++) {
        const float4* ap = (const float4*)(adj  + (b0 + b) * 64 + v * 8);
        const float4* ep = (const float4*)(edge + (b0 + b) * 64 + v * 8);
        float4 a0 = ap[0], a1 = ap[1], e0 = ep[0], e1 = ep[1];
        float4 S0 = *(const float4*)(Xg + 128 + b * 64 + v * 8);
        float4 S1 = *(const float4*)(Xg + 128 + b * 64 + v * 8 + 4);
        Wr[b][0] = a0.x * (S0.x + e0.x); Wr[b][1] = a0.y * (S0.y + e0.y);
        Wr[b][2] = a0.z * (S0.z + e0.z); Wr[b][3] = a0.w * (S0.w + e0.w);
        Wr[b][4] = a1.x * (S1.x + e1.x); Wr[b][5] = a1.y * (S1.y + e1.y);
        Wr[b][6] = a1.z * (S1.z + e1.z); Wr[b][7] = a1.w * (S1.w + e1.w);
    }

    // ================= h1 row v (j-paired)
    u64 h[2][8];
    #pragma unroll
    for (int i = 0; i < 8; i++) { h[0][i] = 0ull; h[1][i] = 0ull; }
    #pragma unroll
    for (int w = 0; w < 8; w++) {
        u64 w0 = pk1(Wr[0][w]), w1p = pk1(Wr[1][w]);
        const ulonglong2* pr0 = (const ulonglong2*)(Xg + 256 + w * 16);
        const ulonglong2* pr1 = (const ulonglong2*)(Xg + 256 + 128 + w * 16);
        #pragma unroll
        for (int jj = 0; jj < 4; jj++) {
            ulonglong2 r0 = pr0[jj], r1 = pr1[jj];
            h[0][jj * 2]     = fma2_(w0, r0.x, h[0][jj * 2]);
            h[0][jj * 2 + 1] = fma2_(w0, r0.y, h[0][jj * 2 + 1]);
            h[1][jj * 2]     = fma2_(w1p, r1.x, h[1][jj * 2]);
            h[1][jj * 2 + 1] = fma2_(w1p, r1.y, h[1][jj * 2 + 1]);
        }
    }
    float hs[2][16];
    #pragma unroll
    for (int i = 0; i < 8; i++) {
        u64 b1p = ((const u64*)s_b1)[i];
        u64 t0 = add2_(h[0][i], b1p), t1 = add2_(h[1][i], b1p);
        up2(t0, hs[0][2 * i], hs[0][2 * i + 1]);
        up2(t1, hs[1][2 * i], hs[1][2 * i + 1]);
    }
    #pragma unroll
    for (int i = 0; i < 16; i++) { hs[0][i] = lrelu(hs[0][i]); hs[1][i] = lrelu(hs[1][i]); }

    // ================= q row v (k-paired)
    u64 qa[2][4];
    #pragma unroll
    for (int i = 0; i < 4; i++) { qa[0][i] = 0ull; qa[1][i] = 0ull; }
    #pragma unroll
    for (int j = 0; j < 16; j++) {
        const ulonglong2* w2r = (const ulonglong2*)s_w2[j];
        ulonglong2 wA = w2r[0], wB = w2r[1];
        u64 hj0 = pk1(hs[0][j]), hj1 = pk1(hs[1][j]);
        qa[0][0] = fma2_(hj0, wA.x, qa[0][0]);
        qa[0][1] = fma2_(hj0, wA.y, qa[0][1]);
        qa[0][2] = fma2_(hj0, wB.x, qa[0][2]);
        qa[0][3] = fma2_(hj0, wB.y, qa[0][3]);
        qa[1][0] = fma2_(hj1, wA.x, qa[1][0]);
        qa[1][1] = fma2_(hj1, wA.y, qa[1][1]);
        qa[1][2] = fma2_(hj1, wB.x, qa[1][2]);
        qa[1][3] = fma2_(hj1, wB.y, qa[1][3]);
    }
    __syncwarp();
    {
        u64* d0 = (u64*)(Xg + 128) + v * 4;
        u64* d1 = (u64*)(Xg + 128) + 32 + v * 4;
        #pragma unroll
        for (int i = 0; i < 4; i++) { d0[i] = qa[0][i]; d1[i] = qa[1][i]; }
    }
    __syncwarp();

    // ================= h2 row v (k-paired), write h2 rows
    {
        u64 h2a[2][4];
        #pragma unroll
        for (int i = 0; i < 4; i++) { h2a[0][i] = 0ull; h2a[1][i] = 0ull; }
        #pragma unroll
        for (int w = 0; w < 8; w++) {
            u64 w0 = pk1(Wr[0][w]), w1p = pk1(Wr[1][w]);
            ulonglong2 r0a = *(const ulonglong2*)(Xg + 128 + w * 8);
            ulonglong2 r0b = *(const ulonglong2*)(Xg + 128 + w * 8 + 4);
            ulonglong2 r1a = *(const ulonglong2*)(Xg + 128 + 64 + w * 8);
            ulonglong2 r1b = *(const ulonglong2*)(Xg + 128 + 64 + w * 8 + 4);
            h2a[0][0] = fma2_(w0, r0a.x, h2a[0][0]);
            h2a[0][1] = fma2_(w0, r0a.y, h2a[0][1]);
            h2a[0][2] = fma2_(w0, r0b.x, h2a[0][2]);
            h2a[0][3] = fma2_(w0, r0b.y, h2a[0][3]);
            h2a[1][0] = fma2_(w1p, r1a.x, h2a[1][0]);
            h2a[1][1] = fma2_(w1p, r1a.y, h2a[1][1]);
            h2a[1][2] = fma2_(w1p, r1b.x, h2a[1][2]);
            h2a[1][3] = fma2_(w1p, r1b.y, h2a[1][3]);
        }
        #pragma unroll
        for (int b = 0; b < 2; b++) {
            u64* dst = (u64*)(Xg + 256) + b * 32 + v * 4;
            #pragma unroll
            for (int i = 0; i < 4; i++) {
                u64 t = add2_(h2a[b][i], ((const u64*)s_b2)[i]);
                float lo, hi; up2(t, lo, hi);
                dst[i] = pk2(lrelu(lo), lrelu(hi));
            }
        }
    }
    __syncwarp();

    // ================= attention pooling: thread v = output channel o
    {
        const ulonglong2* wgr = (const ulonglong2*)s_wg[v];
        ulonglong2 wgA = wgr[0], wgB = wgr[1];
        float d[2][8], ho[2][8], tyu[2][8];
        #pragma unroll
        for (int u = 0; u < 8; u++) {
            #pragma unroll
            for (int b = 0; b < 2; b++) {
                ulonglong2 ra = *(const ulonglong2*)(Xg + 256 + b * 64 + u * 8);
                ulonglong2 rb = *(const ulonglong2*)(Xg + 256 + b * 64 + u * 8 + 4);
                u64 acc = mul2_(wgA.x, ra.x);
                acc = fma2_(wgA.y, ra.y, acc);
                acc = fma2_(wgB.x, rb.x, acc);
                acc = fma2_(wgB.y, rb.y, acc);
                float lo, hi; up2(acc, lo, hi);
                d[b][u] = lo + hi;
                ho[b][u]  = Xg[256 + b * 64 + u * 8 + v];
                tyu[b][u] = Xg[512 + b * 8 + u];
            }
        }
        const float bgv = s_bg[v];
        #pragma unroll
        for (int b = 0; b < 2; b++) {
            float xp = 0.f;
            #pragma unroll
            for (int t = 0; t < 2; t++) {
                float tf = (float)t;
                float L[8], hm[8];
                float mx = -1e30f;
                #pragma unroll
                for (int u = 0; u < 8; u++) {
                    float ma = (tyu[b][u] == tf) ? 1.f : 0.f;
                    L[u] = ma * d[b][u] + bgv;
                    hm[u] = ma * ho[b][u];
                    mx = fmaxf(mx, L[u]);
                }
                float se = 0.f, nu = 0.f;
                #pragma unroll
                for (int u = 0; u < 8; u++) {
                    float e = __expf(L[u] - mx);
                    se += e; nu += e * hm[u];
                }
                xp += nu / se;
            }
            Xg[528 + b * 8 + v] = 0.5f * xp;
        }
    }
    __syncwarp();

    if (v < 2) {
        #pragma unroll
        for (int b = 0; b < 2; b++) {
            float o = s_bf[v];
            #pragma unroll
            for (int c = 0; c < 8; c++) o += Xg[528 + b * 8 + c] * s_wf[v * 8 + c];
            out[(b0 + b) * 2 + v] = o;
        }
    }
}

extern "C" void kernel_launch(void* const* d_in, const int* in_sizes, int n_in,
                              void* d_out, int out_size)
{
    const float* x    = (const float*)d_in[0];
    const float* adj  = (const float*)d_in[1];
    const float* edge = (const float*)d_in[2];
    const float* wb = (const float*)d_in[5];
    const float* bb = (const float*)d_in[6];
    const float* w1 = (const float*)d_in[7];
    const float* b1 = (const float*)d_in[8];
    const float* w2 = (const float*)d_in[9];
    const float* b2 = (const float*)d_in[10];
    const float* wg = (const float*)d_in[11];
    const float* bg = (const float*)d_in[12];
    const float* wf = (const float*)d_in[13];
    const float* bf = (const float*)d_in[14];

    const int B = in_sizes[0] / 264;
    const int grid = B / (2 * PAIRS_PER_BLOCK);
    gcn_kernel<<<grid, NTHREADS>>>(x, adj, edge, wb, bb, w1, b1, w2, b2,
                                   wg, bg, wf, bf, (float*)d_out);
}

// round 3
// speedup vs baseline: 1.7330x; 1.1202x over previous
#include <cuda_runtime.h>

#define PAIRS_PER_BLOCK 8
#define NTHREADS (PAIRS_PER_BLOCK * 8)
#define SLOT 552            // floats per pair slot; 552 % 32 == 8 (bank spread over g)
#define BSTRIDE 268         // floats per batch inside slot; 268 % 32 == 12 (spread over b)

typedef unsigned long long u64;

__device__ __forceinline__ u64 pk2(float a, float b) {
    u64 r; asm("mov.b64 %0,{%1,%2};" : "=l"(r) : "f"(a), "f"(b)); return r;
}
__device__ __forceinline__ u64 pk1(float a) { return pk2(a, a); }
__device__ __forceinline__ void up2(u64 v, float& a, float& b) {
    asm("mov.b64 {%0,%1},%2;" : "=f"(a), "=f"(b) : "l"(v));
}
__device__ __forceinline__ u64 fma2_(u64 a, u64 b, u64 c) {
    u64 d; asm("fma.rn.f32x2 %0,%1,%2,%3;" : "=l"(d) : "l"(a), "l"(b), "l"(c)); return d;
}
__device__ __forceinline__ u64 add2_(u64 a, u64 b) {
    u64 d; asm("add.rn.f32x2 %0,%1,%2;" : "=l"(d) : "l"(a), "l"(b)); return d;
}
__device__ __forceinline__ u64 mul2_(u64 a, u64 b) {
    u64 d; asm("mul.rn.f32x2 %0,%1,%2;" : "=l"(d) : "l"(a), "l"(b)); return d;
}
__device__ __forceinline__ float lrelu(float x) { return fmaxf(x, 0.01f * x); }

__global__ void __launch_bounds__(NTHREADS, 10)
gcn_kernel(const float* __restrict__ x,   const float* __restrict__ adj,
           const float* __restrict__ edge,
           const float* __restrict__ wb,  const float* __restrict__ bb,
           const float* __restrict__ w1,  const float* __restrict__ b1,
           const float* __restrict__ w2,  const float* __restrict__ b2,
           const float* __restrict__ wg,  const float* __restrict__ bg,
           const float* __restrict__ wf,  const float* __restrict__ bf,
           float* __restrict__ out)
{
    // Per-pair slot (SLOT floats):
    //  Phase A (x stage, straight copy): batch bb at bb*BSTRIDE .. +263
    //      node v: type at bb*268 + v*33, feat c at bb*268 + v*33 + 1 + c
    //  ty stash: 536 + bb*8 + v   (outside x region, written before aliasing)
    //  Phase B (aliases x region after phase-1 reads complete):
    //      FkT rows at 0..127, S->q rows at 128..255, p->h2 rows at 256..511,
    //      xp at 512..527
    __shared__ __align__(16) float s_u[PAIRS_PER_BLOCK * SLOT];
    __shared__ __align__(16) float s_w1[32][16];
    __shared__ __align__(16) float s_wbT[32][8];
    __shared__ __align__(16) float s_w2[16][8];
    __shared__ __align__(16) float s_wg[8][8];
    __shared__ __align__(16) float s_bb[8];
    __shared__ __align__(16) float s_b1[16];
    __shared__ __align__(16) float s_b2[8];
    __shared__ float s_bg[8], s_wf[16], s_bf[2];

    const int tid = threadIdx.x;

    for (int i = tid; i < 512; i += NTHREADS) ((float*)s_w1)[i] = w1[i];
    for (int i = tid; i < 256; i += NTHREADS) {
        int c = i >> 3, o = i & 7;
        s_wbT[c][o] = wb[o * 32 + c];
    }
    for (int i = tid; i < 128; i += NTHREADS) ((float*)s_w2)[i] = w2[i];
    if (tid < 64) ((float*)s_wg)[tid] = wg[tid];
    if (tid < 16) { s_b1[tid] = b1[tid]; s_wf[tid] = wf[tid]; }
    if (tid < 8)  { s_bb[tid] = bb[tid]; s_b2[tid] = b2[tid]; s_bg[tid] = bg[tid]; }
    if (tid < 2)  { s_bf[tid] = bf[tid]; }

    {   // straight float4 copy: x tile -> per-batch regions (no transpose, no div/mod chains)
        const float4* xsrc = (const float4*)(x + (size_t)blockIdx.x * (PAIRS_PER_BLOCK * 2 * 264));
        float4* dst4 = (float4*)s_u;
        #pragma unroll 1
        for (int i = tid; i < PAIRS_PER_BLOCK * 2 * 66; i += NTHREADS) {
            int bl = i / 66;                 // local batch 0..15 (mul-shift, cheap)
            int j  = i - bl * 66;            // float4 index within batch
            int pr = bl >> 1, bbx = bl & 1;
            dst4[pr * (SLOT / 4) + bbx * (BSTRIDE / 4) + j] = xsrc[i];
        }
    }
    __syncthreads();

    const int g = tid >> 3;
    const int v = tid & 7;
    const size_t pair = (size_t)blockIdx.x * PAIRS_PER_BLOCK + g;
    const size_t b0 = pair * 2;
    float* Xg = s_u + g * SLOT;

    // stash node types outside the soon-to-be-aliased region
    Xg[536 + 0 * 8 + v] = Xg[0 * BSTRIDE + v * 33];
    Xg[536 + 1 * 8 + v] = Xg[1 * BSTRIDE + v * 33];

    // ================= phase 1: Fk column v (o-paired), p row v (j-paired)
    u64 Fk[2][4], p[2][8];
    #pragma unroll
    for (int i = 0; i < 4; i++) { Fk[0][i] = 0ull; Fk[1][i] = 0ull; }
    #pragma unroll
    for (int i = 0; i < 8; i++) { p[0][i] = 0ull; p[1][i] = 0ull; }

    const float* f0 = Xg + 0 * BSTRIDE + v * 33 + 1;
    const float* f1 = Xg + 1 * BSTRIDE + v * 33 + 1;
    #pragma unroll 8
    for (int c = 0; c < 32; c++) {
        u64 q0 = pk1(f0[c]), q1 = pk1(f1[c]);
        const ulonglong2* w1r = (const ulonglong2*)s_w1[c];
        const ulonglong2* wbr = (const ulonglong2*)s_wbT[c];
        #pragma unroll
        for (int jj = 0; jj < 4; jj++) {
            ulonglong2 w = w1r[jj];
            p[0][jj * 2]     = fma2_(q0, w.x, p[0][jj * 2]);
            p[0][jj * 2 + 1] = fma2_(q0, w.y, p[0][jj * 2 + 1]);
            p[1][jj * 2]     = fma2_(q1, w.x, p[1][jj * 2]);
            p[1][jj * 2 + 1] = fma2_(q1, w.y, p[1][jj * 2 + 1]);
        }
        #pragma unroll
        for (int oo = 0; oo < 2; oo++) {
            ulonglong2 w = wbr[oo];
            Fk[0][oo * 2]     = fma2_(q0, w.x, Fk[0][oo * 2]);
            Fk[0][oo * 2 + 1] = fma2_(q0, w.y, Fk[0][oo * 2 + 1]);
            Fk[1][oo * 2]     = fma2_(q1, w.x, Fk[1][oo * 2]);
            Fk[1][oo * 2 + 1] = fma2_(q1, w.y, Fk[1][oo * 2 + 1]);
        }
    }
    #pragma unroll
    for (int i = 0; i < 4; i++) {
        u64 bbp = ((const u64*)s_bb)[i];
        Fk[0][i] = add2_(Fk[0][i], bbp);
        Fk[1][i] = add2_(Fk[1][i], bbp);
    }

    __syncwarp();   // all feat reads done -> safe to alias x region with exchange buffers
    {
        u64* d0 = (u64*)Xg + v * 4;
        u64* d1 = (u64*)Xg + 32 + v * 4;
        #pragma unroll
        for (int i = 0; i < 4; i++) { d0[i] = Fk[0][i]; d1[i] = Fk[1][i]; }
        u64* p0 = (u64*)(Xg + 256) + v * 8;
        u64* p1 = (u64*)(Xg + 256) + 64 + v * 8;
        #pragma unroll
        for (int i = 0; i < 8; i++) { p0[i] = p[0][i]; p1[i] = p[1][i]; }
    }
    __syncwarp();

    // ================= M column v, softmax over rows i, write S rows
    {
        float fks[2][8];
        #pragma unroll
        for (int i = 0; i < 4; i++) {
            up2(Fk[0][i], fks[0][2 * i], fks[0][2 * i + 1]);
            up2(Fk[1][i], fks[1][2 * i], fks[1][2 * i + 1]);
        }
        u64 Mv[2][4];
        #pragma unroll
        for (int i = 0; i < 4; i++) { Mv[0][i] = 0ull; Mv[1][i] = 0ull; }
        #pragma unroll
        for (int k = 0; k < 8; k++) {
            ulonglong2 r0a = *(const ulonglong2*)(Xg + k * 8);
            ulonglong2 r0b = *(const ulonglong2*)(Xg + k * 8 + 4);
            ulonglong2 r1a = *(const ulonglong2*)(Xg + 64 + k * 8);
            ulonglong2 r1b = *(const ulonglong2*)(Xg + 64 + k * 8 + 4);
            u64 s0 = pk1(fks[0][k]), s1 = pk1(fks[1][k]);
            Mv[0][0] = fma2_(s0, r0a.x, Mv[0][0]);
            Mv[0][1] = fma2_(s0, r0a.y, Mv[0][1]);
            Mv[0][2] = fma2_(s0, r0b.x, Mv[0][2]);
            Mv[0][3] = fma2_(s0, r0b.y, Mv[0][3]);
            Mv[1][0] = fma2_(s1, r1a.x, Mv[1][0]);
            Mv[1][1] = fma2_(s1, r1a.y, Mv[1][1]);
            Mv[1][2] = fma2_(s1, r1b.x, Mv[1][2]);
            Mv[1][3] = fma2_(s1, r1b.y, Mv[1][3]);
        }
        #pragma unroll
        for (int b = 0; b < 2; b++) {
            float m[8];
            #pragma unroll
            for (int i = 0; i < 4; i++) up2(Mv[b][i], m[2 * i], m[2 * i + 1]);
            float mx = m[0];
            #pragma unroll
            for (int i = 1; i < 8; i++) mx = fmaxf(mx, m[i]);
            float se = 0.f;
            #pragma unroll
            for (int i = 0; i < 8; i++) { m[i] = __expf(m[i] - mx); se += m[i]; }
            float inv = 1.f / se;
            #pragma unroll
            for (int i = 0; i < 8; i++) Xg[128 + b * 64 + i * 8 + v] = m[i] * inv;
        }
    }
    __syncwarp();

    // ================= W row v in registers
    float Wr[2][8];
    #pragma unroll
    for (int b = 0; b < 2; b++) {
        const float4* ap = (const float4*)(adj  + (b0 + b) * 64 + v * 8);
        const float4* ep = (const float4*)(edge + (b0 + b) * 64 + v * 8);
        float4 a0 = ap[0], a1 = ap[1], e0 = ep[0], e1 = ep[1];
        float4 S0 = *(const float4*)(Xg + 128 + b * 64 + v * 8);
        float4 S1 = *(const float4*)(Xg + 128 + b * 64 + v * 8 + 4);
        Wr[b][0] = a0.x * (S0.x + e0.x); Wr[b][1] = a0.y * (S0.y + e0.y);
        Wr[b][2] = a0.z * (S0.z + e0.z); Wr[b][3] = a0.w * (S0.w + e0.w);
        Wr[b][4] = a1.x * (S1.x + e1.x); Wr[b][5] = a1.y * (S1.y + e1.y);
        Wr[b][6] = a1.z * (S1.z + e1.z); Wr[b][7] = a1.w * (S1.w + e1.w);
    }

    // ================= h1 row v (j-paired)
    u64 h[2][8];
    #pragma unroll
    for (int i = 0; i < 8; i++) { h[0][i] = 0ull; h[1][i] = 0ull; }
    #pragma unroll
    for (int w = 0; w < 8; w++) {
        u64 w0 = pk1(Wr[0][w]), w1p = pk1(Wr[1][w]);
        const ulonglong2* pr0 = (const ulonglong2*)(Xg + 256 + w * 16);
        const ulonglong2* pr1 = (const ulonglong2*)(Xg + 256 + 128 + w * 16);
        #pragma unroll
        for (int jj = 0; jj < 4; jj++) {
            ulonglong2 r0 = pr0[jj], r1 = pr1[jj];
            h[0][jj * 2]     = fma2_(w0, r0.x, h[0][jj * 2]);
            h[0][jj * 2 + 1] = fma2_(w0, r0.y, h[0][jj * 2 + 1]);
            h[1][jj * 2]     = fma2_(w1p, r1.x, h[1][jj * 2]);
            h[1][jj * 2 + 1] = fma2_(w1p, r1.y, h[1][jj * 2 + 1]);
        }
    }
    float hs[2][16];
    #pragma unroll
    for (int i = 0; i < 8; i++) {
        u64 b1p = ((const u64*)s_b1)[i];
        u64 t0 = add2_(h[0][i], b1p), t1 = add2_(h[1][i], b1p);
        up2(t0, hs[0][2 * i], hs[0][2 * i + 1]);
        up2(t1, hs[1][2 * i], hs[1][2 * i + 1]);
    }
    #pragma unroll
    for (int i = 0; i < 16; i++) { hs[0][i] = lrelu(hs[0][i]); hs[1][i] = lrelu(hs[1][i]); }

    // ================= q row v (k-paired)
    u64 qa[2][4];
    #pragma unroll
    for (int i = 0; i < 4; i++) { qa[0][i] = 0ull; qa[1][i] = 0ull; }
    #pragma unroll
    for (int j = 0; j < 16; j++) {
        const ulonglong2* w2r = (const ulonglong2*)s_w2[j];
        ulonglong2 wA = w2r[0], wB = w2r[1];
        u64 hj0 = pk1(hs[0][j]), hj1 = pk1(hs[1][j]);
        qa[0][0] = fma2_(hj0, wA.x, qa[0][0]);
        qa[0][1] = fma2_(hj0, wA.y, qa[0][1]);
        qa[0][2] = fma2_(hj0, wB.x, qa[0][2]);
        qa[0][3] = fma2_(hj0, wB.y, qa[0][3]);
        qa[1][0] = fma2_(hj1, wA.x, qa[1][0]);
        qa[1][1] = fma2_(hj1, wA.y, qa[1][1]);
        qa[1][2] = fma2_(hj1, wB.x, qa[1][2]);
        qa[1][3] = fma2_(hj1, wB.y, qa[1][3]);
    }
    __syncwarp();   // everyone done reading S before q overwrites it
    {
        u64* d0 = (u64*)(Xg + 128) + v * 4;
        u64* d1 = (u64*)(Xg + 128) + 32 + v * 4;
        #pragma unroll
        for (int i = 0; i < 4; i++) { d0[i] = qa[0][i]; d1[i] = qa[1][i]; }
    }
    __syncwarp();

    // ================= h2 row v (k-paired), write h2 rows
    {
        u64 h2a[2][4];
        #pragma unroll
        for (int i = 0; i < 4; i++) { h2a[0][i] = 0ull; h2a[1][i] = 0ull; }
        #pragma unroll
        for (int w = 0; w < 8; w++) {
            u64 w0 = pk1(Wr[0][w]), w1p = pk1(Wr[1][w]);
            ulonglong2 r0a = *(const ulonglong2*)(Xg + 128 + w * 8);
            ulonglong2 r0b = *(const ulonglong2*)(Xg + 128 + w * 8 + 4);
            ulonglong2 r1a = *(const ulonglong2*)(Xg + 128 + 64 + w * 8);
            ulonglong2 r1b = *(const ulonglong2*)(Xg + 128 + 64 + w * 8 + 4);
            h2a[0][0] = fma2_(w0, r0a.x, h2a[0][0]);
            h2a[0][1] = fma2_(w0, r0a.y, h2a[0][1]);
            h2a[0][2] = fma2_(w0, r0b.x, h2a[0][2]);
            h2a[0][3] = fma2_(w0, r0b.y, h2a[0][3]);
            h2a[1][0] = fma2_(w1p, r1a.x, h2a[1][0]);
            h2a[1][1] = fma2_(w1p, r1a.y, h2a[1][1]);
            h2a[1][2] = fma2_(w1p, r1b.x, h2a[1][2]);
            h2a[1][3] = fma2_(w1p, r1b.y, h2a[1][3]);
        }
        __syncwarp();   // S (q) reads done before h2 overwrites p region readers? p region distinct; guard anyway
        #pragma unroll
        for (int b = 0; b < 2; b++) {
            u64* dst = (u64*)(Xg + 256) + b * 32 + v * 4;
            #pragma unroll
            for (int i = 0; i < 4; i++) {
                u64 t = add2_(h2a[b][i], ((const u64*)s_b2)[i]);
                float lo, hi; up2(t, lo, hi);
                dst[i] = pk2(lrelu(lo), lrelu(hi));
            }
        }
    }
    __syncwarp();

    // ================= attention pooling: thread v = output channel o
    {
        const ulonglong2* wgr = (const ulonglong2*)s_wg[v];
        ulonglong2 wgA = wgr[0], wgB = wgr[1];
        float d[2][8], ho[2][8], tyu[2][8];
        #pragma unroll
        for (int u = 0; u < 8; u++) {
            #pragma unroll
            for (int b = 0; b < 2; b++) {
                ulonglong2 ra = *(const ulonglong2*)(Xg + 256 + b * 64 + u * 8);
                ulonglong2 rb = *(const ulonglong2*)(Xg + 256 + b * 64 + u * 8 + 4);
                u64 acc = mul2_(wgA.x, ra.x);
                acc = fma2_(wgA.y, ra.y, acc);
                acc = fma2_(wgB.x, rb.x, acc);
                acc = fma2_(wgB.y, rb.y, acc);
                float lo, hi; up2(acc, lo, hi);
                d[b][u] = lo + hi;
                ho[b][u]  = Xg[256 + b * 64 + u * 8 + v];
                tyu[b][u] = Xg[536 + b * 8 + u];
            }
        }
        const float bgv = s_bg[v];
        #pragma unroll
        for (int b = 0; b < 2; b++) {
            float xp = 0.f;
            #pragma unroll
            for (int t = 0; t < 2; t++) {
                float tf = (float)t;
                float L[8], hm[8];
                float mx = -1e30f;
                #pragma unroll
                for (int u = 0; u < 8; u++) {
                    float ma = (tyu[b][u] == tf) ? 1.f : 0.f;
                    L[u] = ma * d[b][u] + bgv;
                    hm[u] = ma * ho[b][u];
                    mx = fmaxf(mx, L[u]);
                }
                float se = 0.f, nu = 0.f;
                #pragma unroll
                for (int u = 0; u < 8; u++) {
                    float e = __expf(L[u] - mx);
                    se += e; nu += e * hm[u];
                }
                xp += nu / se;
            }
            Xg[512 + b * 8 + v] = 0.5f * xp;
        }
    }
    __syncwarp();

    if (v < 2) {
        #pragma unroll
        for (int b = 0; b < 2; b++) {
            float o = s_bf[v];
            #pragma unroll
            for (int c = 0; c < 8; c++) o += Xg[512 + b * 8 + c] * s_wf[v * 8 + c];
            out[(b0 + b) * 2 + v] = o;
        }
    }
}

extern "C" void kernel_launch(void* const* d_in, const int* in_sizes, int n_in,
                              void* d_out, int out_size)
{
    const float* x    = (const float*)d_in[0];
    const float* adj  = (const float*)d_in[1];
    const float* edge = (const float*)d_in[2];
    const float* wb = (const float*)d_in[5];
    const float* bb = (const float*)d_in[6];
    const float* w1 = (const float*)d_in[7];
    const float* b1 = (const float*)d_in[8];
    const float* w2 = (const float*)d_in[9];
    const float* b2 = (const float*)d_in[10];
    const float* wg = (const float*)d_in[11];
    const float* bg = (const float*)d_in[12];
    const float* wf = (const float*)d_in[13];
    const float* bf = (const float*)d_in[14];

    const int B = in_sizes[0] / 264;
    const int grid = B / (2 * PAIRS_PER_BLOCK);
    gcn_kernel<<<grid, NTHREADS>>>(x, adj, edge, wb, bb, w1, b1, w2, b2,
                                   wg, bg, wf, bf, (float*)d_out);
}